// round 15
// baseline (speedup 1.0000x reference)
#include <cuda_runtime.h>
#include <math.h>
#include <stdint.h>

#define Bc 2
#define Nc 1024
#define Dc 384
#define Hc 8
#define HDc 48
#define DFFc 512
#define Lc 4
#define Mrows (Bc*Nc)        // 2048
#define BNN (Bc*Nc*Nc)
#define TBL 4096

// ---------------- scratch ----------------
__device__ float g_x[Bc*Nc*Dc];
__device__ float g_h[Bc*Nc*Dc];
__device__ float g_q[Bc*Nc*Dc];
__device__ float g_k[Bc*Nc*Dc];
__device__ float g_v[Bc*Nc*Dc];
__device__ float g_attnv[Bc*Nc*Dc];
__device__ float g_mlogits[BNN];                  // 8 MB merged logits
__device__ float g_S[Bc*Nc*Nc*3];                 // 24 MB colsum_m(orientation)
__device__ float g_bias[(size_t)Lc*BNN];          // 32 MB dis-bias (mask folded)
__device__ float g_tbl[Lc][TBL+1];
__device__ float g_v3d[Mrows*3];
__device__ float g_frame[Mrows*3];
__device__ float g_ff[Mrows*DFFc];

// ---------------- helpers ----------------
__device__ __forceinline__ void mma_tf32(float d[4], const uint32_t a[4], const uint32_t b[2]) {
    asm volatile("mma.sync.aligned.m16n8k8.row.col.f32.tf32.tf32.f32 "
        "{%0,%1,%2,%3}, {%4,%5,%6,%7}, {%8,%9}, {%0,%1,%2,%3};"
        : "+f"(d[0]), "+f"(d[1]), "+f"(d[2]), "+f"(d[3])
        : "r"(a[0]), "r"(a[1]), "r"(a[2]), "r"(a[3]), "r"(b[0]), "r"(b[1]));
}
__device__ __forceinline__ void cp16(uint32_t saddr, const void* g) {
    asm volatile("cp.async.cg.shared.global [%0], [%1], 16;" :: "r"(saddr), "l"(g) : "memory");
}
__device__ __forceinline__ void cp_commit() {
    asm volatile("cp.async.commit_group;" ::: "memory");
}
__device__ __forceinline__ void cp_wait1() {
    asm volatile("cp.async.wait_group 1;" ::: "memory");
}
__device__ __forceinline__ void cp_wait0() {
    asm volatile("cp.async.wait_group 0;" ::: "memory");
}

// ---------------- S[b,i,j,n] = sum_m orientation[b,i,j,m,n] ----------------
__global__ void precomp_S(const float* __restrict__ orient, float* __restrict__ S) {
    int idx = blockIdx.x * blockDim.x + threadIdx.x;
    if (idx >= BNN) return;
    const float* o = orient + (size_t)idx * 9;
    S[idx*3+0] = o[0] + o[3] + o[6];
    S[idx*3+1] = o[1] + o[4] + o[7];
    S[idx*3+2] = o[2] + o[5] + o[8];
}

// ---------------- per-layer RBF bias lookup table ----------------
__global__ void table_kernel(const float* __restrict__ Wmlp, const float* __restrict__ bmlp) {
    int i = blockIdx.x * blockDim.x + threadIdx.x;
    if (i >= Lc*(TBL+1)) return;
    int l = i / (TBL+1), t = i % (TBL+1);
    float d = 20.f * (float)t / (float)TBL;
    float acc = bmlp[l];
    const float invsig = 0.8f;
#pragma unroll
    for (int r = 0; r < 16; r++) {
        float mu = (20.f/15.f) * (float)r;
        float u = (d - mu) * invsig;
        acc += Wmlp[l*16 + r] * expf(-u*u);
    }
    g_tbl[l][t] = acc;
}

// ---------------- bias_all[l][p] = mask? -1e9 : lerp(table_l, dist[p]) ----------------
__global__ void bias_kernel(const float* __restrict__ dist, const int* __restrict__ mask,
                            float* __restrict__ bias_all) {
    int p = blockIdx.x * blockDim.x + threadIdx.x;
    if (p >= BNN) return;
    float d = dist[p];
    bool m0 = (mask[p] == 0);
    float fi = fmaxf(d, 0.f) * ((float)TBL / 20.f);
    int i0 = min((int)fi, TBL-1);
    float fr = fi - (float)i0;
#pragma unroll
    for (int l = 0; l < Lc; l++) {
        float t0 = g_tbl[l][i0], t1 = g_tbl[l][i0+1];
        float v = t0 + fr * (t1 - t0);
        bias_all[(size_t)l*BNN + p] = m0 ? -1e9f : v;
    }
}

// ---------------- LayerNorm ----------------
__global__ void ln_kernel(const float* __restrict__ x, const float* __restrict__ g,
                          const float* __restrict__ b, float* __restrict__ out) {
    int row = blockIdx.x;
    const float* xr = x + (size_t)row*Dc;
    float v[3];
    float s = 0.f, s2 = 0.f;
#pragma unroll
    for (int i = 0; i < 3; i++) {
        v[i] = xr[threadIdx.x + i*128];
        s += v[i]; s2 += v[i]*v[i];
    }
    __shared__ float sh1[128], sh2[128];
    sh1[threadIdx.x] = s; sh2[threadIdx.x] = s2;
    __syncthreads();
    for (int st = 64; st > 0; st >>= 1) {
        if (threadIdx.x < st) { sh1[threadIdx.x] += sh1[threadIdx.x+st]; sh2[threadIdx.x] += sh2[threadIdx.x+st]; }
        __syncthreads();
    }
    float mean = sh1[0] * (1.f/Dc);
    float var  = sh2[0] * (1.f/Dc) - mean*mean;
    float inv  = rsqrtf(var + 1e-5f);
#pragma unroll
    for (int i = 0; i < 3; i++) {
        int c = threadIdx.x + i*128;
        out[(size_t)row*Dc + c] = (v[i] - mean) * inv * g[c] + b[c];
    }
}

// ---------------- TF32 MMA GEMM: 64x64 tile, BK=32, cp.async double buffer ----------------
// 256 threads = 8 warps; warp tile 16x32 (1 m-frag x 4 n-frags). wm=(warp&3)*16, wn=(warp>>2)*32.
__device__ __forceinline__ void gemm_mma_core(
    const float* __restrict__ A, int K,
    const float* __restrict__ W, const float* __restrict__ bias,
    float* __restrict__ C, const float* __restrict__ Cres, int Nout, int relu,
    const float* __restrict__ tailA, const float* __restrict__ tailW,
    uint32_t* sm)
{
    int bm = blockIdx.y * 64, bn = blockIdx.x * 64;
    int tid = threadIdx.x;
    int warp = tid >> 5, lane = tid & 31;
    int wm = (warp & 3) * 16, wn = (warp >> 2) * 32;
    int g = lane >> 2, t = lane & 3;
    uint32_t sbase = (uint32_t)__cvta_generic_to_shared(sm);
    int ktiles = K >> 5;

    auto issue_tile = [&](int kt) {
        int k0 = kt << 5;
        uint32_t Ab = sbase + (kt & 1) * 9216;
        uint32_t Bb = sbase + 18432 + (kt & 1) * 9216;
#pragma unroll
        for (int it = 0; it < 2; it++) {
            int idx = tid + it*256;
            int m = idx >> 3, ca4 = (idx & 7) * 4;
            cp16(Ab + (m*36 + ca4)*4, A + (size_t)(bm+m)*K + k0 + ca4);
            int kk = idx >> 4, cb4 = (idx & 15) * 4;
            cp16(Bb + (kk*72 + cb4)*4, W + (size_t)(k0+kk)*Nout + bn + cb4);
        }
        cp_commit();
    };

    float acc[4][4] = {};
    issue_tile(0);
    for (int kt = 0; kt < ktiles; kt++) {
        if (kt + 1 < ktiles) { issue_tile(kt+1); cp_wait1(); }
        else cp_wait0();
        __syncthreads();
        const uint32_t* Ab = sm + (kt & 1) * 2304;
        const uint32_t* Bb = sm + 4608 + (kt & 1) * 2304;
#pragma unroll
        for (int k8 = 0; k8 < 4; k8++) {
            int kb = k8 * 8;
            uint32_t a[4], bf[4][2];
            a[0] = Ab[(wm + g)*36 + kb + t];
            a[1] = Ab[(wm + 8 + g)*36 + kb + t];
            a[2] = Ab[(wm + g)*36 + kb + t + 4];
            a[3] = Ab[(wm + 8 + g)*36 + kb + t + 4];
#pragma unroll
            for (int j = 0; j < 4; j++) {
                int cn = wn + 8*j + g;
                bf[j][0] = Bb[(kb+t)*72 + cn];
                bf[j][1] = Bb[(kb+t+4)*72 + cn];
            }
#pragma unroll
            for (int j = 0; j < 4; j++)
                mma_tf32(acc[j], a, bf[j]);
        }
        __syncthreads();
    }
#pragma unroll
    for (int j = 0; j < 4; j++) {
        int ng = bn + wn + 8*j + 2*t;
        float b0 = bias[ng], b1 = bias[ng+1];
        float tw[3][2];
        if (tailA) {
#pragma unroll
            for (int r = 0; r < 3; r++) {
                tw[r][0] = __ldg(&tailW[r*Nout + ng]);
                tw[r][1] = __ldg(&tailW[r*Nout + ng + 1]);
            }
        }
#pragma unroll
        for (int rr = 0; rr < 2; rr++) {
            int mg = bm + wm + g + 8*rr;
            float o0 = acc[j][rr*2+0] + b0;
            float o1 = acc[j][rr*2+1] + b1;
            if (tailA) {
                float f0 = __ldg(&tailA[mg*3]), f1 = __ldg(&tailA[mg*3+1]), f2 = __ldg(&tailA[mg*3+2]);
                o0 += f0*tw[0][0] + f1*tw[1][0] + f2*tw[2][0];
                o1 += f0*tw[0][1] + f1*tw[1][1] + f2*tw[2][1];
            }
            if (relu) { o0 = fmaxf(o0, 0.f); o1 = fmaxf(o1, 0.f); }
            if (Cres) {
                float2 rv = *(const float2*)&Cres[(size_t)mg*Nout + ng];
                o0 += rv.x; o1 += rv.y;
            }
            float2 o = {o0, o1};
            *(float2*)&C[(size_t)mg*Nout + ng] = o;
        }
    }
}

__global__ __launch_bounds__(256) void gemm_mma_kernel(
    const float* __restrict__ A, int K,
    const float* __restrict__ W, const float* __restrict__ bias,
    float* __restrict__ C, const float* __restrict__ Cres, int Nout, int relu,
    const float* __restrict__ tailA, const float* __restrict__ tailW) {
    __shared__ uint32_t sm[9216];
    gemm_mma_core(A, K, W, bias, C, Cres, Nout, relu, tailA, tailW, sm);
}

__global__ __launch_bounds__(256) void gemm3_mma_kernel(const float* __restrict__ A,
                             const float* __restrict__ W0, const float* __restrict__ W1, const float* __restrict__ W2,
                             const float* __restrict__ b0, const float* __restrict__ b1, const float* __restrict__ b2,
                             float* __restrict__ C0, float* __restrict__ C1, float* __restrict__ C2) {
    __shared__ uint32_t sm[9216];
    int z = blockIdx.z;
    const float* W = (z == 0) ? W0 : (z == 1) ? W1 : W2;
    const float* b = (z == 0) ? b0 : (z == 1) ? b1 : b2;
    float* C = (z == 0) ? C0 : (z == 1) ? C1 : C2;
    gemm_mma_core(A, Dc, W, b, C, nullptr, Dc, 0, nullptr, nullptr, sm);
}

// ---------------- v3d: warp-per-row h[row] @ W3 + b3 ----------------
__global__ void v3_kernel(const float* __restrict__ h, const float* __restrict__ W3,
                          const float* __restrict__ b3, float* __restrict__ out) {
    int warp = (blockIdx.x * blockDim.x + threadIdx.x) >> 5;
    int lane = threadIdx.x & 31;
    if (warp >= Mrows) return;
    const float* hr = h + (size_t)warp*Dc;
    float s0 = 0.f, s1 = 0.f, s2 = 0.f;
#pragma unroll
    for (int i = 0; i < 12; i++) {
        int c = lane + i*32;
        float hv = hr[c];
        s0 += hv * W3[c*3+0];
        s1 += hv * W3[c*3+1];
        s2 += hv * W3[c*3+2];
    }
#pragma unroll
    for (int off = 16; off > 0; off >>= 1) {
        s0 += __shfl_down_sync(0xffffffffu, s0, off);
        s1 += __shfl_down_sync(0xffffffffu, s1, off);
        s2 += __shfl_down_sync(0xffffffffu, s2, off);
    }
    if (lane == 0) {
        out[warp*3+0] = s0 + b3[0];
        out[warp*3+1] = s1 + b3[1];
        out[warp*3+2] = s2 + b3[2];
    }
}

// ---------------- flash attention: no P smem round-trip (C->A fragment shfl permute) ----------------
__global__ __launch_bounds__(128) void flash_kernel(
    const float* __restrict__ q, const float* __restrict__ k, const float* __restrict__ v,
    const float* __restrict__ bias, float* __restrict__ attn_out)
{
    __shared__ uint32_t qs[64*52];   // [q][d]  stride 52
    __shared__ uint32_t ks[64*52];   // [k'][d] stride 52
    __shared__ uint32_t vs[64*56];   // [k'][d] stride 56
    int bid = blockIdx.x;
    int b = bid >> 7, h = (bid >> 4) & 7, q0 = (bid & 15) * 64;
    int tid = threadIdx.x;
    int warp = tid >> 5, lane = tid & 31;
    int g = lane >> 2, t = lane & 3;
    int wq = warp * 16;

    float4 rk[6], rv[6];
    auto ldg6 = [&](const float* src, int row0, float4* dst) {
#pragma unroll
        for (int j = 0; j < 6; j++) {
            int i = tid + j*128;
            int r = i / 12, c = (i % 12) * 4;
            dst[j] = *(const float4*)&src[(size_t)(b*Nc + row0 + r)*Dc + h*HDc + c];
        }
    };
    auto sts6 = [&](uint32_t* buf, int stride, const float4* src) {
#pragma unroll
        for (int j = 0; j < 6; j++) {
            int i = tid + j*128;
            int r = i / 12, c = (i % 12) * 4;
            buf[r*stride + c]     = __float_as_uint(src[j].x);
            buf[r*stride + c + 1] = __float_as_uint(src[j].y);
            buf[r*stride + c + 2] = __float_as_uint(src[j].z);
            buf[r*stride + c + 3] = __float_as_uint(src[j].w);
        }
    };

    ldg6(q, q0, rk);  sts6(qs, 52, rk);
    ldg6(k, 0, rk);   sts6(ks, 52, rk);
    ldg6(v, 0, rv);   sts6(vs, 56, rv);
    __syncthreads();

    float O[6][4] = {};
    float rsum0 = 0.f, rsum1 = 0.f;
    const float scale = 0.14433756729740643f;
    int src0 = (lane & ~3) | (t >> 1);
    bool odd = (t & 1);

    for (int kt = 0; kt < 16; kt++) {
        int k0 = kt * 64;
        if (kt < 15) { ldg6(k, k0 + 64, rk); ldg6(v, k0 + 64, rv); }
        float sacc[8][4] = {};
#pragma unroll
        for (int d8 = 0; d8 < 6; d8++) {
            uint32_t a[4];
            a[0] = qs[(wq + g)*52 + d8*8 + t];
            a[1] = qs[(wq + g + 8)*52 + d8*8 + t];
            a[2] = qs[(wq + g)*52 + d8*8 + t + 4];
            a[3] = qs[(wq + g + 8)*52 + d8*8 + t + 4];
#pragma unroll
            for (int j = 0; j < 8; j++) {
                uint32_t bb[2];
                bb[0] = ks[(8*j + g)*52 + d8*8 + t];
                bb[1] = ks[(8*j + g)*52 + d8*8 + t + 4];
                mma_tf32(sacc[j], a, bb);
            }
        }
#pragma unroll
        for (int j = 0; j < 8; j++) {
            int c = 8*j + 2*t;
            size_t row0 = (size_t)(b*Nc + q0 + wq + g);
            float2 d0 = *(const float2*)&bias[row0*Nc + k0 + c];
            float2 d1 = *(const float2*)&bias[(row0 + 8)*Nc + k0 + c];
            float e00 = __expf(sacc[j][0]*scale + d0.x);
            float e01 = __expf(sacc[j][1]*scale + d0.y);
            float e10 = __expf(sacc[j][2]*scale + d1.x);
            float e11 = __expf(sacc[j][3]*scale + d1.y);
            rsum0 += e00 + e01; rsum1 += e10 + e11;
            float a0v = __shfl_sync(0xffffffffu, e00, src0);
            float a0w = __shfl_sync(0xffffffffu, e01, src0);
            float a2v = __shfl_sync(0xffffffffu, e00, src0 + 2);
            float a2w = __shfl_sync(0xffffffffu, e01, src0 + 2);
            float a1v = __shfl_sync(0xffffffffu, e10, src0);
            float a1w = __shfl_sync(0xffffffffu, e11, src0);
            float a3v = __shfl_sync(0xffffffffu, e10, src0 + 2);
            float a3w = __shfl_sync(0xffffffffu, e11, src0 + 2);
            uint32_t pa[4];
            pa[0] = __float_as_uint(odd ? a0w : a0v);
            pa[1] = __float_as_uint(odd ? a1w : a1v);
            pa[2] = __float_as_uint(odd ? a2w : a2v);
            pa[3] = __float_as_uint(odd ? a3w : a3v);
#pragma unroll
            for (int dn = 0; dn < 6; dn++) {
                uint32_t bb[2];
                bb[0] = vs[(8*j + t)*56 + 8*dn + g];
                bb[1] = vs[(8*j + t + 4)*56 + 8*dn + g];
                mma_tf32(O[dn], pa, bb);
            }
        }
        __syncthreads();
        if (kt < 15) {
            sts6(ks, 52, rk);
            sts6(vs, 56, rv);
            __syncthreads();
        }
    }
#pragma unroll
    for (int off = 1; off <= 2; off <<= 1) {
        rsum0 += __shfl_xor_sync(0xffffffffu, rsum0, off);
        rsum1 += __shfl_xor_sync(0xffffffffu, rsum1, off);
    }
    float rinv0 = 1.f / rsum0, rinv1 = 1.f / rsum1;
#pragma unroll
    for (int dn = 0; dn < 6; dn++) {
        int c = 8*dn + 2*t;
        float2 o0 = {O[dn][0]*rinv0, O[dn][1]*rinv0};
        float2 o1 = {O[dn][2]*rinv1, O[dn][3]*rinv1};
        *(float2*)&attn_out[(size_t)(b*Nc + q0 + wq + g)*Dc + h*HDc + c]     = o0;
        *(float2*)&attn_out[(size_t)(b*Nc + q0 + wq + g + 8)*Dc + h*HDc + c] = o1;
    }
}

// ---------------- qkfull: merged logits via cp.async double-buffered chunks ----------------
__global__ __launch_bounds__(128) void qkfull_kernel(
    const float* __restrict__ q, const float* __restrict__ k,
    const float* __restrict__ bias, float* __restrict__ mlog)
{
    extern __shared__ uint32_t dsm[];
    int qid = blockIdx.x;
    int b = qid >> 8, q0 = ((qid >> 4) & 15) * 64, k0 = (qid & 15) * 64;
    int tid = threadIdx.x;
    int warp = tid >> 5, lane = tid & 31;
    int g = lane >> 2, t = lane & 3;
    int wq = warp * 16;
    uint32_t sbase = (uint32_t)__cvta_generic_to_shared(dsm);

    auto issue = [&](int dt) {
        int d0 = dt * 64;
        uint32_t qb = sbase + ((dt & 1) ? 8704u*4u : 0u);
        uint32_t kb = qb + 4352u*4u;
#pragma unroll
        for (int it = 0; it < 8; it++) {
            int idx = tid + it*128;
            int r = idx >> 4, c4 = (idx & 15) * 4;
            cp16(qb + (r*68 + c4)*4, q + (size_t)(b*Nc + q0 + r)*Dc + d0 + c4);
            cp16(kb + (r*68 + c4)*4, k + (size_t)(b*Nc + k0 + r)*Dc + d0 + c4);
        }
        cp_commit();
    };

    float sacc[8][4] = {};
    issue(0);
    for (int dt = 0; dt < 6; dt++) {
        if (dt + 1 < 6) { issue(dt+1); cp_wait1(); }
        else cp_wait0();
        __syncthreads();
        const uint32_t* qs = dsm + (dt & 1) * 8704;
        const uint32_t* ks = qs + 4352;
#pragma unroll
        for (int d8 = 0; d8 < 8; d8++) {
            uint32_t a[4];
            a[0] = qs[(wq + g)*68 + d8*8 + t];
            a[1] = qs[(wq + g + 8)*68 + d8*8 + t];
            a[2] = qs[(wq + g)*68 + d8*8 + t + 4];
            a[3] = qs[(wq + g + 8)*68 + d8*8 + t + 4];
#pragma unroll
            for (int j = 0; j < 8; j++) {
                uint32_t bb[2];
                bb[0] = ks[(8*j + g)*68 + d8*8 + t];
                bb[1] = ks[(8*j + g)*68 + d8*8 + t + 4];
                mma_tf32(sacc[j], a, bb);
            }
        }
        __syncthreads();
    }
    const float scale = 0.14433756729740643f;
#pragma unroll
    for (int j = 0; j < 8; j++) {
        int c = 8*j + 2*t;
        size_t row0 = (size_t)(b*Nc + q0 + wq + g);
        float2 d0 = *(const float2*)&bias[row0*Nc + k0 + c];
        float2 d1 = *(const float2*)&bias[(row0 + 8)*Nc + k0 + c];
        float2 w0 = {sacc[j][0]*scale + 8.f*d0.x, sacc[j][1]*scale + 8.f*d0.y};
        float2 w1 = {sacc[j][2]*scale + 8.f*d1.x, sacc[j][3]*scale + 8.f*d1.y};
        *(float2*)&mlog[row0*Nc + k0 + c]       = w0;
        *(float2*)&mlog[(row0 + 8)*Nc + k0 + c] = w1;
    }
}

#define QK_SMEM (17408 * 4)   // 69632 B

// ---------------- merged softmax + geometric frame (warp-shuffle reductions) ----------------
__global__ void merged_frame_kernel(const float* __restrict__ mlog,
                                    const float* __restrict__ ad, const float* __restrict__ S,
                                    const float* __restrict__ v3d, float* __restrict__ frame) {
    int row = blockIdx.x;          // b*N + i
    int b = row >> 10;
    int tid = threadIdx.x;         // 256
    int wid = tid >> 5, lane = tid & 31;
    __shared__ float probs[Nc];
    __shared__ float v3s[Nc*3];
    __shared__ float shw[8];
    __shared__ float shf[24];
    for (int tn = tid; tn < 768; tn += 256)
        *(float4*)&v3s[tn*4] = *(const float4*)&v3d[b*Nc*3 + tn*4];
    float4 lv = *(const float4*)&mlog[(size_t)row*Nc + tid*4];
    float e0 = __expf(lv.x), e1 = __expf(lv.y), e2 = __expf(lv.z), e3 = __expf(lv.w);
    float sum = e0 + e1 + e2 + e3;
#pragma unroll
    for (int off = 16; off > 0; off >>= 1) sum += __shfl_xor_sync(0xffffffffu, sum, off);
    if (lane == 0) shw[wid] = sum;
    __syncthreads();
    float tot = shw[0]+shw[1]+shw[2]+shw[3]+shw[4]+shw[5]+shw[6]+shw[7];
    float inv = 1.f / tot;
    float4 pr = {e0*inv, e1*inv, e2*inv, e3*inv};
    *(float4*)&probs[tid*4] = pr;
    __syncthreads();
    float cx = 0.f, cy = 0.f, cz = 0.f;
    {
        int j0 = tid * 4;
        size_t base = ((size_t)row*Nc + j0)*3;
        float4 A0 = *(const float4*)&ad[base];
        float4 A1 = *(const float4*)&ad[base+4];
        float4 A2 = *(const float4*)&ad[base+8];
        float4 S0 = *(const float4*)&S[base];
        float4 S1 = *(const float4*)&S[base+4];
        float4 S2 = *(const float4*)&S[base+8];
        float af[12] = {A0.x,A0.y,A0.z,A0.w,A1.x,A1.y,A1.z,A1.w,A2.x,A2.y,A2.z,A2.w};
        float sf[12] = {S0.x,S0.y,S0.z,S0.w,S1.x,S1.y,S1.z,S1.w,S2.x,S2.y,S2.z,S2.w};
#pragma unroll
        for (int jj = 0; jj < 4; jj++) {
            int j = j0 + jj;
            float m = probs[j];
            float ax = af[jj*3+0], ay = af[jj*3+1], az = af[jj*3+2];
            float bx = sf[jj*3+0]*v3s[j*3+0];
            float by = sf[jj*3+1]*v3s[j*3+1];
            float bz = sf[jj*3+2]*v3s[j*3+2];
            cx += m * (ay*bz - az*by);
            cy += m * (az*bx - ax*bz);
            cz += m * (ax*by - ay*bx);
        }
    }
#pragma unroll
    for (int off = 16; off > 0; off >>= 1) {
        cx += __shfl_xor_sync(0xffffffffu, cx, off);
        cy += __shfl_xor_sync(0xffffffffu, cy, off);
        cz += __shfl_xor_sync(0xffffffffu, cz, off);
    }
    if (lane == 0) { shf[wid*3+0] = cx; shf[wid*3+1] = cy; shf[wid*3+2] = cz; }
    __syncthreads();
    if (tid < 3) {
        float s = 0.f;
#pragma unroll
        for (int w = 0; w < 8; w++) s += shf[w*3 + tid];
        frame[row*3 + tid] = s * (1.f/Nc);
    }
}

// ---------------- host driver ----------------
extern "C" void kernel_launch(void* const* d_in, const int* in_sizes, int n_in,
                              void* d_out, int out_size) {
    const float* x_rigid = (const float*)d_in[0];
    const float* ad      = (const float*)d_in[1];
    const float* orient  = (const float*)d_in[2];
    const float* dist    = (const float*)d_in[3];
    const int*   amask   = (const int*)  d_in[4];
    const float* Wq   = (const float*)d_in[5];
    const float* bq   = (const float*)d_in[6];
    const float* Wk   = (const float*)d_in[7];
    const float* bk   = (const float*)d_in[8];
    const float* Wv   = (const float*)d_in[9];
    const float* bv   = (const float*)d_in[10];
    const float* W3   = (const float*)d_in[11];
    const float* b3   = (const float*)d_in[12];
    const float* Wmlp = (const float*)d_in[13];
    const float* bmlp = (const float*)d_in[14];
    const float* Wfc  = (const float*)d_in[15];
    const float* bfc  = (const float*)d_in[16];
    const float* Wff1 = (const float*)d_in[17];
    const float* bff1 = (const float*)d_in[18];
    const float* Wff2 = (const float*)d_in[19];
    const float* bff2 = (const float*)d_in[20];
    const float* ln1g = (const float*)d_in[21];
    const float* ln1b = (const float*)d_in[22];
    const float* ln2g = (const float*)d_in[23];
    const float* ln2b = (const float*)d_in[24];

    float *px, *ph, *pq, *pk, *pv, *pav, *pml, *pS, *pbias, *pv3, *pfr, *pff;
    cudaGetSymbolAddress((void**)&px,  g_x);
    cudaGetSymbolAddress((void**)&ph,  g_h);
    cudaGetSymbolAddress((void**)&pq,  g_q);
    cudaGetSymbolAddress((void**)&pk,  g_k);
    cudaGetSymbolAddress((void**)&pv,  g_v);
    cudaGetSymbolAddress((void**)&pav, g_attnv);
    cudaGetSymbolAddress((void**)&pml, g_mlogits);
    cudaGetSymbolAddress((void**)&pS,  g_S);
    cudaGetSymbolAddress((void**)&pbias, g_bias);
    cudaGetSymbolAddress((void**)&pv3, g_v3d);
    cudaGetSymbolAddress((void**)&pfr, g_frame);
    cudaGetSymbolAddress((void**)&pff, g_ff);

    static bool inited = false;
    static cudaStream_t sA = nullptr, sB = nullptr;
    static cudaEvent_t e0, e1, e2, e3, e4;
    if (!inited) {
        cudaStreamCreateWithFlags(&sA, cudaStreamNonBlocking);
        cudaStreamCreateWithFlags(&sB, cudaStreamNonBlocking);
        cudaEventCreateWithFlags(&e0, cudaEventDisableTiming);
        cudaEventCreateWithFlags(&e1, cudaEventDisableTiming);
        cudaEventCreateWithFlags(&e2, cudaEventDisableTiming);
        cudaEventCreateWithFlags(&e3, cudaEventDisableTiming);
        cudaEventCreateWithFlags(&e4, cudaEventDisableTiming);
        cudaFuncSetAttribute(qkfull_kernel, cudaFuncAttributeMaxDynamicSharedMemorySize, QK_SMEM);
        inited = true;
    }

    // fork side streams off the capture (legacy) stream
    cudaEventRecord(e0, 0);
    cudaStreamWaitEvent(sA, e0, 0);
    cudaStreamWaitEvent(sB, e0, 0);

    table_kernel<<<(Lc*(TBL+1)+255)/256, 256, 0, sA>>>(Wmlp, bmlp);
    bias_kernel<<<(BNN+255)/256, 256, 0, sA>>>(dist, amask, pbias);
    cudaEventRecord(e3, sA);
    precomp_S<<<(BNN+255)/256, 256, 0, sB>>>(orient, pS);
    cudaEventRecord(e4, sB);
    cudaStreamWaitEvent(sA, e4, 0);

    dim3 gQKV3(Dc/64, Mrows/64, 3);   // (6,32,3)
    dim3 gFC(Dc/64, Mrows/64);        // (6,32)
    dim3 gFF1(DFFc/64, Mrows/64);     // (8,32)

    for (int l = 0; l < Lc; l++) {
        const float* xin = (l == 0) ? x_rigid : px;
        float* ff2out = (l == Lc-1) ? (float*)d_out : px;
        ln_kernel<<<Mrows, 128>>>(xin, ln1g + l*Dc, ln1b + l*Dc, ph);
        cudaEventRecord(e0, 0);
        cudaStreamWaitEvent(sA, e0, 0);
        v3_kernel<<<Mrows/8, 256, 0, sA>>>(ph, W3 + l*Dc*3, b3 + l*3, pv3);
        gemm3_mma_kernel<<<gQKV3, 256>>>(ph, Wq + l*Dc*Dc, Wk + l*Dc*Dc, Wv + l*Dc*Dc,
                                         bq + l*Dc, bk + l*Dc, bv + l*Dc, pq, pk, pv);
        cudaEventRecord(e1, 0);
        cudaStreamWaitEvent(sA, e1, 0);
        qkfull_kernel<<<512, 128, QK_SMEM, sA>>>(pq, pk, pbias + (size_t)l*BNN, pml);
        merged_frame_kernel<<<Mrows, 256, 0, sA>>>(pml, ad, pS, pv3, pfr);
        cudaEventRecord(e2, sA);
        if (l == 0) cudaStreamWaitEvent(0, e3, 0);
        flash_kernel<<<256, 128>>>(pq, pk, pv, pbias + (size_t)l*BNN, pav);
        cudaStreamWaitEvent(0, e2, 0);
        gemm_mma_kernel<<<gFC, 256>>>(pav, Dc, Wfc + (size_t)l*(Dc+3)*Dc, bfc + l*Dc,
                                      px, xin, Dc, 0, pfr, Wfc + (size_t)l*(Dc+3)*Dc + (size_t)Dc*Dc);
        ln_kernel<<<Mrows, 128>>>(px, ln2g + l*Dc, ln2b + l*Dc, ph);
        gemm_mma_kernel<<<gFF1, 256>>>(ph, Dc, Wff1 + (size_t)l*Dc*DFFc, bff1 + l*DFFc,
                                       pff, nullptr, DFFc, 1, nullptr, nullptr);
        gemm_mma_kernel<<<gFC, 256>>>(pff, DFFc, Wff2 + (size_t)l*DFFc*Dc, bff2 + l*Dc,
                                      ff2out, px, Dc, 0, nullptr, nullptr);
    }
}

// round 17
// speedup vs baseline: 1.0697x; 1.0697x over previous
#include <cuda_runtime.h>
#include <math.h>
#include <stdint.h>

#define Bc 2
#define Nc 1024
#define Dc 384
#define Hc 8
#define HDc 48
#define DFFc 512
#define Lc 4
#define Mrows (Bc*Nc)        // 2048
#define BNN (Bc*Nc*Nc)
#define TBL 4096

// ---------------- scratch ----------------
__device__ float g_x[Bc*Nc*Dc];
__device__ float g_h[Bc*Nc*Dc];
__device__ float g_q[Bc*Nc*Dc];
__device__ float g_k[Bc*Nc*Dc];
__device__ float g_v[Bc*Nc*Dc];
__device__ float g_attnv[Bc*Nc*Dc];
__device__ float g_mlogits[BNN];                  // 8 MB merged logits
__device__ float g_S[Bc*Nc*Nc*3];                 // 24 MB colsum_m(orientation)
__device__ float g_bias[(size_t)Lc*BNN];          // 32 MB dis-bias (mask folded)
__device__ float g_tbl[Lc][TBL+1];
__device__ float g_v3d[Mrows*3];
__device__ float g_frame[Mrows*3];
__device__ float g_ff[Mrows*DFFc];

// ---------------- helpers ----------------
__device__ __forceinline__ void mma_tf32(float d[4], const uint32_t a[4], const uint32_t b[2]) {
    asm volatile("mma.sync.aligned.m16n8k8.row.col.f32.tf32.tf32.f32 "
        "{%0,%1,%2,%3}, {%4,%5,%6,%7}, {%8,%9}, {%0,%1,%2,%3};"
        : "+f"(d[0]), "+f"(d[1]), "+f"(d[2]), "+f"(d[3])
        : "r"(a[0]), "r"(a[1]), "r"(a[2]), "r"(a[3]), "r"(b[0]), "r"(b[1]));
}
__device__ __forceinline__ void cp16(uint32_t saddr, const void* g) {
    asm volatile("cp.async.cg.shared.global [%0], [%1], 16;" :: "r"(saddr), "l"(g) : "memory");
}
__device__ __forceinline__ void cp_commit() {
    asm volatile("cp.async.commit_group;" ::: "memory");
}
__device__ __forceinline__ void cp_wait1() {
    asm volatile("cp.async.wait_group 1;" ::: "memory");
}
__device__ __forceinline__ void cp_wait0() {
    asm volatile("cp.async.wait_group 0;" ::: "memory");
}

// ---------------- S[b,i,j,n] = sum_m orientation[b,i,j,m,n] ----------------
__global__ void precomp_S(const float* __restrict__ orient, float* __restrict__ S) {
    int idx = blockIdx.x * blockDim.x + threadIdx.x;
    if (idx >= BNN) return;
    const float* o = orient + (size_t)idx * 9;
    S[idx*3+0] = o[0] + o[3] + o[6];
    S[idx*3+1] = o[1] + o[4] + o[7];
    S[idx*3+2] = o[2] + o[5] + o[8];
}

// ---------------- per-layer RBF bias lookup table ----------------
__global__ void table_kernel(const float* __restrict__ Wmlp, const float* __restrict__ bmlp) {
    int i = blockIdx.x * blockDim.x + threadIdx.x;
    if (i >= Lc*(TBL+1)) return;
    int l = i / (TBL+1), t = i % (TBL+1);
    float d = 20.f * (float)t / (float)TBL;
    float acc = bmlp[l];
    const float invsig = 0.8f;
#pragma unroll
    for (int r = 0; r < 16; r++) {
        float mu = (20.f/15.f) * (float)r;
        float u = (d - mu) * invsig;
        acc += Wmlp[l*16 + r] * expf(-u*u);
    }
    g_tbl[l][t] = acc;
}

// ---------------- bias_all[l][p] = mask? -1e9 : lerp(table_l, dist[p]) ----------------
__global__ void bias_kernel(const float* __restrict__ dist, const int* __restrict__ mask,
                            float* __restrict__ bias_all) {
    int p = blockIdx.x * blockDim.x + threadIdx.x;
    if (p >= BNN) return;
    float d = dist[p];
    bool m0 = (mask[p] == 0);
    float fi = fmaxf(d, 0.f) * ((float)TBL / 20.f);
    int i0 = min((int)fi, TBL-1);
    float fr = fi - (float)i0;
#pragma unroll
    for (int l = 0; l < Lc; l++) {
        float t0 = g_tbl[l][i0], t1 = g_tbl[l][i0+1];
        float v = t0 + fr * (t1 - t0);
        bias_all[(size_t)l*BNN + p] = m0 ? -1e9f : v;
    }
}

// ---------------- LayerNorm ----------------
__global__ void ln_kernel(const float* __restrict__ x, const float* __restrict__ g,
                          const float* __restrict__ b, float* __restrict__ out) {
    int row = blockIdx.x;
    const float* xr = x + (size_t)row*Dc;
    float v[3];
    float s = 0.f, s2 = 0.f;
#pragma unroll
    for (int i = 0; i < 3; i++) {
        v[i] = xr[threadIdx.x + i*128];
        s += v[i]; s2 += v[i]*v[i];
    }
    __shared__ float sh1[128], sh2[128];
    sh1[threadIdx.x] = s; sh2[threadIdx.x] = s2;
    __syncthreads();
    for (int st = 64; st > 0; st >>= 1) {
        if (threadIdx.x < st) { sh1[threadIdx.x] += sh1[threadIdx.x+st]; sh2[threadIdx.x] += sh2[threadIdx.x+st]; }
        __syncthreads();
    }
    float mean = sh1[0] * (1.f/Dc);
    float var  = sh2[0] * (1.f/Dc) - mean*mean;
    float inv  = rsqrtf(var + 1e-5f);
#pragma unroll
    for (int i = 0; i < 3; i++) {
        int c = threadIdx.x + i*128;
        out[(size_t)row*Dc + c] = (v[i] - mean) * inv * g[c] + b[c];
    }
}

// ---------------- TF32 MMA GEMM: 64x64 tile, BK=32, 3-stage cp.async pipeline ----------------
// 128 threads (4 warps, 32x32 warp tiles). One __syncthreads per k-tile.
// smem: 3 stages x (A 64x36 + B 32x72) = 3 x 4608 words = 55296 B (dynamic).
#define GEMM_SMEM 55296
__device__ __forceinline__ void gemm_mma_core(
    const float* __restrict__ A, int K,
    const float* __restrict__ W, const float* __restrict__ bias,
    float* __restrict__ C, const float* __restrict__ Cres, int Nout, int relu,
    const float* __restrict__ tailA, const float* __restrict__ tailW,
    uint32_t* sm)
{
    int bm = blockIdx.y * 64, bn = blockIdx.x * 64;
    int tid = threadIdx.x;
    int warp = tid >> 5, lane = tid & 31;
    int wm = (warp & 1) * 32, wn = (warp >> 1) * 32;
    int g = lane >> 2, t = lane & 3;
    uint32_t sbase = (uint32_t)__cvta_generic_to_shared(sm);
    int ktiles = K >> 5;

    auto issue_tile = [&](int kt, int st) {
        int k0 = kt << 5;
        uint32_t Ab = sbase + st * 18432;
        uint32_t Bb = Ab + 9216;
#pragma unroll
        for (int it = 0; it < 4; it++) {
            int idx = tid + it*128;
            int m = idx >> 3, ca4 = (idx & 7) * 4;
            cp16(Ab + (m*36 + ca4)*4, A + (size_t)(bm+m)*K + k0 + ca4);
            int kk = idx >> 4, cb4 = (idx & 15) * 4;
            cp16(Bb + (kk*72 + cb4)*4, W + (size_t)(k0+kk)*Nout + bn + cb4);
        }
        cp_commit();
    };

    float acc[2][4][4] = {};
    issue_tile(0, 0);
    if (ktiles > 1) issue_tile(1, 1);
    int st = 0, sti = 2;
    for (int kt = 0; kt < ktiles; kt++) {
        if (kt + 1 < ktiles) cp_wait1();
        else cp_wait0();
        __syncthreads();                      // stage st data visible; all warps past mma(kt-1)
        if (kt + 2 < ktiles) {
            issue_tile(kt + 2, sti);
            if (++sti == 3) sti = 0;
        }
        const uint32_t* Ab = sm + st * 4608;
        const uint32_t* Bb = Ab + 2304;
#pragma unroll
        for (int k8 = 0; k8 < 4; k8++) {
            int kb = k8 * 8;
            uint32_t a[2][4], bf[4][2];
#pragma unroll
            for (int i = 0; i < 2; i++) {
                int r0 = wm + 16*i + g;
                a[i][0] = Ab[r0*36 + kb + t];
                a[i][1] = Ab[(r0+8)*36 + kb + t];
                a[i][2] = Ab[r0*36 + kb + t + 4];
                a[i][3] = Ab[(r0+8)*36 + kb + t + 4];
            }
#pragma unroll
            for (int j = 0; j < 4; j++) {
                int cn = wn + 8*j + g;
                bf[j][0] = Bb[(kb+t)*72 + cn];
                bf[j][1] = Bb[(kb+t+4)*72 + cn];
            }
#pragma unroll
            for (int i = 0; i < 2; i++)
#pragma unroll
                for (int j = 0; j < 4; j++)
                    mma_tf32(acc[i][j], a[i], bf[j]);
        }
        if (++st == 3) st = 0;
    }
#pragma unroll
    for (int j = 0; j < 4; j++) {
        int ng = bn + wn + 8*j + 2*t;
        float b0 = bias[ng], b1 = bias[ng+1];
        float tw[3][2];
        if (tailA) {
#pragma unroll
            for (int r = 0; r < 3; r++) {
                tw[r][0] = __ldg(&tailW[r*Nout + ng]);
                tw[r][1] = __ldg(&tailW[r*Nout + ng + 1]);
            }
        }
#pragma unroll
        for (int i = 0; i < 2; i++) {
#pragma unroll
            for (int rr = 0; rr < 2; rr++) {
                int mg = bm + wm + 16*i + g + 8*rr;
                float o0 = acc[i][j][rr*2+0] + b0;
                float o1 = acc[i][j][rr*2+1] + b1;
                if (tailA) {
                    float f0 = __ldg(&tailA[mg*3]), f1 = __ldg(&tailA[mg*3+1]), f2 = __ldg(&tailA[mg*3+2]);
                    o0 += f0*tw[0][0] + f1*tw[1][0] + f2*tw[2][0];
                    o1 += f0*tw[0][1] + f1*tw[1][1] + f2*tw[2][1];
                }
                if (relu) { o0 = fmaxf(o0, 0.f); o1 = fmaxf(o1, 0.f); }
                if (Cres) {
                    float2 rv = *(const float2*)&Cres[(size_t)mg*Nout + ng];
                    o0 += rv.x; o1 += rv.y;
                }
                float2 o = {o0, o1};
                *(float2*)&C[(size_t)mg*Nout + ng] = o;
            }
        }
    }
}

__global__ __launch_bounds__(128) void gemm_mma_kernel(
    const float* __restrict__ A, int K,
    const float* __restrict__ W, const float* __restrict__ bias,
    float* __restrict__ C, const float* __restrict__ Cres, int Nout, int relu,
    const float* __restrict__ tailA, const float* __restrict__ tailW) {
    extern __shared__ uint32_t smg[];
    gemm_mma_core(A, K, W, bias, C, Cres, Nout, relu, tailA, tailW, smg);
}

__global__ __launch_bounds__(128) void gemm3_mma_kernel(const float* __restrict__ A,
                             const float* __restrict__ W0, const float* __restrict__ W1, const float* __restrict__ W2,
                             const float* __restrict__ b0, const float* __restrict__ b1, const float* __restrict__ b2,
                             float* __restrict__ C0, float* __restrict__ C1, float* __restrict__ C2) {
    extern __shared__ uint32_t smg[];
    int z = blockIdx.z;
    const float* W = (z == 0) ? W0 : (z == 1) ? W1 : W2;
    const float* b = (z == 0) ? b0 : (z == 1) ? b1 : b2;
    float* C = (z == 0) ? C0 : (z == 1) ? C1 : C2;
    gemm_mma_core(A, Dc, W, b, C, nullptr, Dc, 0, nullptr, nullptr, smg);
}

// ---------------- v3d: warp-per-row h[row] @ W3 + b3 ----------------
__global__ void v3_kernel(const float* __restrict__ h, const float* __restrict__ W3,
                          const float* __restrict__ b3, float* __restrict__ out) {
    int warp = (blockIdx.x * blockDim.x + threadIdx.x) >> 5;
    int lane = threadIdx.x & 31;
    if (warp >= Mrows) return;
    const float* hr = h + (size_t)warp*Dc;
    float s0 = 0.f, s1 = 0.f, s2 = 0.f;
#pragma unroll
    for (int i = 0; i < 12; i++) {
        int c = lane + i*32;
        float hv = hr[c];
        s0 += hv * W3[c*3+0];
        s1 += hv * W3[c*3+1];
        s2 += hv * W3[c*3+2];
    }
#pragma unroll
    for (int off = 16; off > 0; off >>= 1) {
        s0 += __shfl_down_sync(0xffffffffu, s0, off);
        s1 += __shfl_down_sync(0xffffffffu, s1, off);
        s2 += __shfl_down_sync(0xffffffffu, s2, off);
    }
    if (lane == 0) {
        out[warp*3+0] = s0 + b3[0];
        out[warp*3+1] = s1 + b3[1];
        out[warp*3+2] = s2 + b3[2];
    }
}

// ---------------- combined attention (dynamic smem) ----------------
// flash (blocks 0..255): reg-staged k/v prefetch, 2 syncs/tile.
__device__ void flash_part(uint32_t* dsm,
    const float* __restrict__ q, const float* __restrict__ k, const float* __restrict__ v,
    const float* __restrict__ bias, float* __restrict__ attn_out, int bid)
{
    uint32_t* qs = dsm;              // [q][d]  stride 52
    uint32_t* ks = dsm + 3328;       // [k'][d] stride 52
    uint32_t* vs = dsm + 6656;       // [k'][d] stride 56
    uint32_t* ps = dsm + 10240;      // [q][k'] stride 68
    int b = bid >> 7, h = (bid >> 4) & 7, q0 = (bid & 15) * 64;
    int tid = threadIdx.x;
    int warp = tid >> 5, lane = tid & 31;
    int g = lane >> 2, t = lane & 3;
    int wq = warp * 16;

    float4 rk[6], rv[6];
    auto ldg6 = [&](const float* src, int row0, float4* dst) {
#pragma unroll
        for (int j = 0; j < 6; j++) {
            int i = tid + j*128;
            int r = i / 12, c = (i % 12) * 4;
            dst[j] = *(const float4*)&src[(size_t)(b*Nc + row0 + r)*Dc + h*HDc + c];
        }
    };
    auto sts6 = [&](uint32_t* buf, int stride, const float4* src) {
#pragma unroll
        for (int j = 0; j < 6; j++) {
            int i = tid + j*128;
            int r = i / 12, c = (i % 12) * 4;
            buf[r*stride + c]     = __float_as_uint(src[j].x);
            buf[r*stride + c + 1] = __float_as_uint(src[j].y);
            buf[r*stride + c + 2] = __float_as_uint(src[j].z);
            buf[r*stride + c + 3] = __float_as_uint(src[j].w);
        }
    };

    ldg6(q, q0, rk);  sts6(qs, 52, rk);
    ldg6(k, 0, rk);   sts6(ks, 52, rk);
    ldg6(v, 0, rv);
    __syncthreads();

    float O[6][4] = {};
    float rsum0 = 0.f, rsum1 = 0.f;
    const float scale = 0.14433756729740643f;

    for (int kt = 0; kt < 16; kt++) {
        int k0 = kt * 64;
        float sacc[8][4] = {};
#pragma unroll
        for (int d8 = 0; d8 < 6; d8++) {
            uint32_t a[4];
            a[0] = qs[(wq + g)*52 + d8*8 + t];
            a[1] = qs[(wq + g + 8)*52 + d8*8 + t];
            a[2] = qs[(wq + g)*52 + d8*8 + t + 4];
            a[3] = qs[(wq + g + 8)*52 + d8*8 + t + 4];
#pragma unroll
            for (int j = 0; j < 8; j++) {
                uint32_t bb[2];
                bb[0] = ks[(8*j + g)*52 + d8*8 + t];
                bb[1] = ks[(8*j + g)*52 + d8*8 + t + 4];
                mma_tf32(sacc[j], a, bb);
            }
        }
#pragma unroll
        for (int j = 0; j < 8; j++) {
            int c = 8*j + 2*t;
            size_t row0 = (size_t)(b*Nc + q0 + wq + g);
            float2 d0 = *(const float2*)&bias[row0*Nc + k0 + c];
            float2 d1 = *(const float2*)&bias[(row0 + 8)*Nc + k0 + c];
            float e00 = __expf(sacc[j][0]*scale + d0.x);
            float e01 = __expf(sacc[j][1]*scale + d0.y);
            float e10 = __expf(sacc[j][2]*scale + d1.x);
            float e11 = __expf(sacc[j][3]*scale + d1.y);
            rsum0 += e00 + e01; rsum1 += e10 + e11;
            ps[(wq + g)*68 + c]         = __float_as_uint(e00);
            ps[(wq + g)*68 + c + 1]     = __float_as_uint(e01);
            ps[(wq + g + 8)*68 + c]     = __float_as_uint(e10);
            ps[(wq + g + 8)*68 + c + 1] = __float_as_uint(e11);
        }
        sts6(vs, 56, rv);
        if (kt < 15) ldg6(k, k0 + 64, rk);
        __syncthreads();
#pragma unroll
        for (int j8 = 0; j8 < 8; j8++) {
            uint32_t a[4];
            a[0] = ps[(wq + g)*68 + 8*j8 + t];
            a[1] = ps[(wq + g + 8)*68 + 8*j8 + t];
            a[2] = ps[(wq + g)*68 + 8*j8 + t + 4];
            a[3] = ps[(wq + g + 8)*68 + 8*j8 + t + 4];
#pragma unroll
            for (int dn = 0; dn < 6; dn++) {
                uint32_t bb[2];
                bb[0] = vs[(8*j8 + t)*56 + 8*dn + g];
                bb[1] = vs[(8*j8 + t + 4)*56 + 8*dn + g];
                mma_tf32(O[dn], a, bb);
            }
        }
        if (kt < 15) {
            sts6(ks, 52, rk);
            ldg6(v, k0 + 64, rv);
            __syncthreads();
        }
    }
#pragma unroll
    for (int off = 1; off <= 2; off <<= 1) {
        rsum0 += __shfl_xor_sync(0xffffffffu, rsum0, off);
        rsum1 += __shfl_xor_sync(0xffffffffu, rsum1, off);
    }
    float rinv0 = 1.f / rsum0, rinv1 = 1.f / rsum1;
#pragma unroll
    for (int dn = 0; dn < 6; dn++) {
        int c = 8*dn + 2*t;
        float2 o0 = {O[dn][0]*rinv0, O[dn][1]*rinv0};
        float2 o1 = {O[dn][2]*rinv1, O[dn][3]*rinv1};
        *(float2*)&attn_out[(size_t)(b*Nc + q0 + wq + g)*Dc + h*HDc + c]     = o0;
        *(float2*)&attn_out[(size_t)(b*Nc + q0 + wq + g + 8)*Dc + h*HDc + c] = o1;
    }
}

// qkfull (blocks 256..767): cp.async double-buffered 64-dim chunks
__device__ void qkfull_part(uint32_t* dsm,
    const float* __restrict__ q, const float* __restrict__ k,
    const float* __restrict__ bias, float* __restrict__ mlog, int qid)
{
    int b = qid >> 8, q0 = ((qid >> 4) & 15) * 64, k0 = (qid & 15) * 64;
    int tid = threadIdx.x;
    int warp = tid >> 5, lane = tid & 31;
    int g = lane >> 2, t = lane & 3;
    int wq = warp * 16;
    uint32_t sbase = (uint32_t)__cvta_generic_to_shared(dsm);

    auto issue = [&](int dt) {
        int d0 = dt * 64;
        uint32_t qb = sbase + ((dt & 1) ? 8704u*4u : 0u);
        uint32_t kb = qb + 4352u*4u;
#pragma unroll
        for (int it = 0; it < 8; it++) {
            int idx = tid + it*128;
            int r = idx >> 4, c4 = (idx & 15) * 4;
            cp16(qb + (r*68 + c4)*4, q + (size_t)(b*Nc + q0 + r)*Dc + d0 + c4);
            cp16(kb + (r*68 + c4)*4, k + (size_t)(b*Nc + k0 + r)*Dc + d0 + c4);
        }
        cp_commit();
    };

    float sacc[8][4] = {};
    issue(0);
    for (int dt = 0; dt < 6; dt++) {
        if (dt + 1 < 6) { issue(dt+1); cp_wait1(); }
        else cp_wait0();
        __syncthreads();
        const uint32_t* qs = dsm + (dt & 1) * 8704;
        const uint32_t* ks = qs + 4352;
#pragma unroll
        for (int d8 = 0; d8 < 8; d8++) {
            uint32_t a[4];
            a[0] = qs[(wq + g)*68 + d8*8 + t];
            a[1] = qs[(wq + g + 8)*68 + d8*8 + t];
            a[2] = qs[(wq + g)*68 + d8*8 + t + 4];
            a[3] = qs[(wq + g + 8)*68 + d8*8 + t + 4];
#pragma unroll
            for (int j = 0; j < 8; j++) {
                uint32_t bb[2];
                bb[0] = ks[(8*j + g)*68 + d8*8 + t];
                bb[1] = ks[(8*j + g)*68 + d8*8 + t + 4];
                mma_tf32(sacc[j], a, bb);
            }
        }
        __syncthreads();
    }
    const float scale = 0.14433756729740643f;
#pragma unroll
    for (int j = 0; j < 8; j++) {
        int c = 8*j + 2*t;
        size_t row0 = (size_t)(b*Nc + q0 + wq + g);
        float2 d0 = *(const float2*)&bias[row0*Nc + k0 + c];
        float2 d1 = *(const float2*)&bias[(row0 + 8)*Nc + k0 + c];
        float2 w0 = {sacc[j][0]*scale + 8.f*d0.x, sacc[j][1]*scale + 8.f*d0.y};
        float2 w1 = {sacc[j][2]*scale + 8.f*d1.x, sacc[j][3]*scale + 8.f*d1.y};
        *(float2*)&mlog[row0*Nc + k0 + c]       = w0;
        *(float2*)&mlog[(row0 + 8)*Nc + k0 + c] = w1;
    }
}

__global__ __launch_bounds__(128) void attn_kernel(
    const float* __restrict__ q, const float* __restrict__ k, const float* __restrict__ v,
    const float* __restrict__ bias, float* __restrict__ attn_out, float* __restrict__ mlog)
{
    extern __shared__ uint32_t dsm[];
    int bx = blockIdx.x;
    if (bx < 256) flash_part(dsm, q, k, v, bias, attn_out, bx);
    else          qkfull_part(dsm, q, k, bias, mlog, bx - 256);
}

#define ATTN_SMEM (17408 * 4)   // 69632 B

// ---------------- merged softmax + geometric frame (warp-shuffle reductions) ----------------
__global__ void merged_frame_kernel(const float* __restrict__ mlog,
                                    const float* __restrict__ ad, const float* __restrict__ S,
                                    const float* __restrict__ v3d, float* __restrict__ frame) {
    int row = blockIdx.x;          // b*N + i
    int b = row >> 10;
    int tid = threadIdx.x;         // 256
    int wid = tid >> 5, lane = tid & 31;
    __shared__ float probs[Nc];
    __shared__ float v3s[Nc*3];
    __shared__ float shw[8];
    __shared__ float shf[24];
    for (int tn = tid; tn < 768; tn += 256)
        *(float4*)&v3s[tn*4] = *(const float4*)&v3d[b*Nc*3 + tn*4];
    float4 lv = *(const float4*)&mlog[(size_t)row*Nc + tid*4];
    float e0 = __expf(lv.x), e1 = __expf(lv.y), e2 = __expf(lv.z), e3 = __expf(lv.w);
    float sum = e0 + e1 + e2 + e3;
#pragma unroll
    for (int off = 16; off > 0; off >>= 1) sum += __shfl_xor_sync(0xffffffffu, sum, off);
    if (lane == 0) shw[wid] = sum;
    __syncthreads();
    float tot = shw[0]+shw[1]+shw[2]+shw[3]+shw[4]+shw[5]+shw[6]+shw[7];
    float inv = 1.f / tot;
    float4 pr = {e0*inv, e1*inv, e2*inv, e3*inv};
    *(float4*)&probs[tid*4] = pr;
    __syncthreads();
    float cx = 0.f, cy = 0.f, cz = 0.f;
    {
        int j0 = tid * 4;
        size_t base = ((size_t)row*Nc + j0)*3;
        float4 A0 = *(const float4*)&ad[base];
        float4 A1 = *(const float4*)&ad[base+4];
        float4 A2 = *(const float4*)&ad[base+8];
        float4 S0 = *(const float4*)&S[base];
        float4 S1 = *(const float4*)&S[base+4];
        float4 S2 = *(const float4*)&S[base+8];
        float af[12] = {A0.x,A0.y,A0.z,A0.w,A1.x,A1.y,A1.z,A1.w,A2.x,A2.y,A2.z,A2.w};
        float sf[12] = {S0.x,S0.y,S0.z,S0.w,S1.x,S1.y,S1.z,S1.w,S2.x,S2.y,S2.z,S2.w};
#pragma unroll
        for (int jj = 0; jj < 4; jj++) {
            int j = j0 + jj;
            float m = probs[j];
            float ax = af[jj*3+0], ay = af[jj*3+1], az = af[jj*3+2];
            float bx = sf[jj*3+0]*v3s[j*3+0];
            float by = sf[jj*3+1]*v3s[j*3+1];
            float bz = sf[jj*3+2]*v3s[j*3+2];
            cx += m * (ay*bz - az*by);
            cy += m * (az*bx - ax*bz);
            cz += m * (ax*by - ay*bx);
        }
    }
#pragma unroll
    for (int off = 16; off > 0; off >>= 1) {
        cx += __shfl_xor_sync(0xffffffffu, cx, off);
        cy += __shfl_xor_sync(0xffffffffu, cy, off);
        cz += __shfl_xor_sync(0xffffffffu, cz, off);
    }
    if (lane == 0) { shf[wid*3+0] = cx; shf[wid*3+1] = cy; shf[wid*3+2] = cz; }
    __syncthreads();
    if (tid < 3) {
        float s = 0.f;
#pragma unroll
        for (int w = 0; w < 8; w++) s += shf[w*3 + tid];
        frame[row*3 + tid] = s * (1.f/Nc);
    }
}

// ---------------- host driver (single stream, as in R13 best) ----------------
extern "C" void kernel_launch(void* const* d_in, const int* in_sizes, int n_in,
                              void* d_out, int out_size) {
    const float* x_rigid = (const float*)d_in[0];
    const float* ad      = (const float*)d_in[1];
    const float* orient  = (const float*)d_in[2];
    const float* dist    = (const float*)d_in[3];
    const int*   amask   = (const int*)  d_in[4];
    const float* Wq   = (const float*)d_in[5];
    const float* bq   = (const float*)d_in[6];
    const float* Wk   = (const float*)d_in[7];
    const float* bk   = (const float*)d_in[8];
    const float* Wv   = (const float*)d_in[9];
    const float* bv   = (const float*)d_in[10];
    const float* W3   = (const float*)d_in[11];
    const float* b3   = (const float*)d_in[12];
    const float* Wmlp = (const float*)d_in[13];
    const float* bmlp = (const float*)d_in[14];
    const float* Wfc  = (const float*)d_in[15];
    const float* bfc  = (const float*)d_in[16];
    const float* Wff1 = (const float*)d_in[17];
    const float* bff1 = (const float*)d_in[18];
    const float* Wff2 = (const float*)d_in[19];
    const float* bff2 = (const float*)d_in[20];
    const float* ln1g = (const float*)d_in[21];
    const float* ln1b = (const float*)d_in[22];
    const float* ln2g = (const float*)d_in[23];
    const float* ln2b = (const float*)d_in[24];

    float *px, *ph, *pq, *pk, *pv, *pav, *pml, *pS, *pbias, *pv3, *pfr, *pff;
    cudaGetSymbolAddress((void**)&px,  g_x);
    cudaGetSymbolAddress((void**)&ph,  g_h);
    cudaGetSymbolAddress((void**)&pq,  g_q);
    cudaGetSymbolAddress((void**)&pk,  g_k);
    cudaGetSymbolAddress((void**)&pv,  g_v);
    cudaGetSymbolAddress((void**)&pav, g_attnv);
    cudaGetSymbolAddress((void**)&pml, g_mlogits);
    cudaGetSymbolAddress((void**)&pS,  g_S);
    cudaGetSymbolAddress((void**)&pbias, g_bias);
    cudaGetSymbolAddress((void**)&pv3, g_v3d);
    cudaGetSymbolAddress((void**)&pfr, g_frame);
    cudaGetSymbolAddress((void**)&pff, g_ff);

    static bool inited = false;
    if (!inited) {
        cudaFuncSetAttribute(attn_kernel, cudaFuncAttributeMaxDynamicSharedMemorySize, ATTN_SMEM);
        cudaFuncSetAttribute(gemm_mma_kernel, cudaFuncAttributeMaxDynamicSharedMemorySize, GEMM_SMEM);
        cudaFuncSetAttribute(gemm3_mma_kernel, cudaFuncAttributeMaxDynamicSharedMemorySize, GEMM_SMEM);
        inited = true;
    }

    precomp_S<<<(BNN+255)/256, 256>>>(orient, pS);
    table_kernel<<<(Lc*(TBL+1)+255)/256, 256>>>(Wmlp, bmlp);
    bias_kernel<<<(BNN+255)/256, 256>>>(dist, amask, pbias);

    dim3 gQKV3(Dc/64, Mrows/64, 3);   // (6,32,3)
    dim3 gFC(Dc/64, Mrows/64);        // (6,32)
    dim3 gFF1(DFFc/64, Mrows/64);     // (8,32)

    for (int l = 0; l < Lc; l++) {
        const float* xin = (l == 0) ? x_rigid : px;
        float* ff2out = (l == Lc-1) ? (float*)d_out : px;
        ln_kernel<<<Mrows, 128>>>(xin, ln1g + l*Dc, ln1b + l*Dc, ph);
        gemm3_mma_kernel<<<gQKV3, 128, GEMM_SMEM>>>(ph, Wq + l*Dc*Dc, Wk + l*Dc*Dc, Wv + l*Dc*Dc,
                                                    bq + l*Dc, bk + l*Dc, bv + l*Dc, pq, pk, pv);
        v3_kernel<<<Mrows/8, 256>>>(ph, W3 + l*Dc*3, b3 + l*3, pv3);
        attn_kernel<<<768, 128, ATTN_SMEM>>>(pq, pk, pv, pbias + (size_t)l*BNN, pav, pml);
        merged_frame_kernel<<<Mrows, 256>>>(pml, ad, pS, pv3, pfr);
        gemm_mma_kernel<<<gFC, 128, GEMM_SMEM>>>(pav, Dc, Wfc + (size_t)l*(Dc+3)*Dc, bfc + l*Dc,
                                      px, xin, Dc, 0, pfr, Wfc + (size_t)l*(Dc+3)*Dc + (size_t)Dc*Dc);
        ln_kernel<<<Mrows, 128>>>(px, ln2g + l*Dc, ln2b + l*Dc, ph);
        gemm_mma_kernel<<<gFF1, 128, GEMM_SMEM>>>(ph, Dc, Wff1 + (size_t)l*Dc*DFFc, bff1 + l*DFFc,
                                       pff, nullptr, DFFc, 1, nullptr, nullptr);
        gemm_mma_kernel<<<gFC, 128, GEMM_SMEM>>>(pff, DFFc, Wff2 + (size_t)l*DFFc*Dc, bff2 + l*Dc,
                                      ff2out, px, Dc, 0, nullptr, nullptr);
    }
}